// round 1
// baseline (speedup 1.0000x reference)
#include <cuda_runtime.h>

#define Bn 256
#define Sn 196
#define Dn 2048
#define Hn 512

// Scratch (no cudaMalloc allowed): att_h [B,H], weight [B,S]
__device__ float g_att_h[Bn * Hn];
__device__ float g_weight[Bn * Sn];

// Accurate fast tanh: 1 - 2/(e^{2x}+1). Handles +-inf limits correctly,
// absolute error ~1e-6 (MUFU.EX2 based), no cancellation blowup near 0
// in the absolute sense (which is what propagates through the score sum).
__device__ __forceinline__ float fast_tanh(float x) {
    float t = __expf(2.0f * x);
    return 1.0f - 2.0f / (t + 1.0f);
}

// ---------------------------------------------------------------------------
// Kernel 1: att_h[b,n] = sum_d h[b,d] * W[n,d] + bias[n]
// M=256, N=512, K=2048. 32x32 tile, BK=32, 128 threads, 4x2 per thread.
// Grid: (N/32=16, M/32=8) = 128 blocks -> ~full chip for the fp32 FFMA floor.
// ---------------------------------------------------------------------------
__global__ __launch_bounds__(128) void k_h2att(const float* __restrict__ A,
                                               const float* __restrict__ W,
                                               const float* __restrict__ bias) {
    __shared__ float As[32 * 33];  // [k][m]
    __shared__ float Bs[32 * 33];  // [k][n]
    const int tid = threadIdx.x;
    const int tx = tid & 15;   // n group (2 cols)
    const int ty = tid >> 4;   // m group (4 rows)
    const int m0 = blockIdx.y * 32;
    const int n0 = blockIdx.x * 32;

    float acc[4][2] = {};

    for (int k0 = 0; k0 < Dn; k0 += 32) {
#pragma unroll
        for (int i = 0; i < 8; i++) {
            int idx = i * 128 + tid;
            int r = idx >> 5;      // row within tile (m or n)
            int c = idx & 31;      // k within tile (contiguous -> coalesced)
            As[c * 33 + r] = A[(m0 + r) * Dn + k0 + c];
            Bs[c * 33 + r] = W[(n0 + r) * Dn + k0 + c];
        }
        __syncthreads();
#pragma unroll
        for (int k = 0; k < 32; k++) {
            float a0 = As[k * 33 + ty * 4 + 0];
            float a1 = As[k * 33 + ty * 4 + 1];
            float a2 = As[k * 33 + ty * 4 + 2];
            float a3 = As[k * 33 + ty * 4 + 3];
            float b0 = Bs[k * 33 + tx * 2 + 0];
            float b1 = Bs[k * 33 + tx * 2 + 1];
            acc[0][0] += a0 * b0; acc[0][1] += a0 * b1;
            acc[1][0] += a1 * b0; acc[1][1] += a1 * b1;
            acc[2][0] += a2 * b0; acc[2][1] += a2 * b1;
            acc[3][0] += a3 * b0; acc[3][1] += a3 * b1;
        }
        __syncthreads();
    }

#pragma unroll
    for (int i = 0; i < 4; i++) {
#pragma unroll
        for (int j = 0; j < 2; j++) {
            int n = n0 + tx * 2 + j;
            g_att_h[(m0 + ty * 4 + i) * Hn + n] = acc[i][j] + bias[n];
        }
    }
}

// ---------------------------------------------------------------------------
// Kernel 2: per-batch scores + masked softmax.
//   scores[b,s] = sum_h tanh(p[b,s,h] + att_h[b,h]) * w_alpha[h] + b_alpha
//   weight = softmax(scores); weight *= mask; weight /= sum(weight)
// 1 block (256 threads, 8 warps) per batch. Each warp owns score slots.
// ---------------------------------------------------------------------------
__global__ __launch_bounds__(256) void k_scores(const float* __restrict__ p_att,
                                                const float* __restrict__ w_alpha,
                                                const float* __restrict__ b_alpha,
                                                const float* __restrict__ mask) {
    __shared__ float ah[Hn];
    __shared__ float wa[Hn];
    __shared__ float sc[Sn];
    __shared__ float red[8];

    const int b = blockIdx.x;
    const int tid = threadIdx.x;
    const int lane = tid & 31;
    const int warp = tid >> 5;

    ah[tid]       = g_att_h[b * Hn + tid];
    ah[tid + 256] = g_att_h[b * Hn + tid + 256];
    wa[tid]       = w_alpha[tid];
    wa[tid + 256] = w_alpha[tid + 256];
    __syncthreads();

    const float balpha = b_alpha[0];

    // Scores: warp per s, float4 along h.
    for (int s = warp; s < Sn; s += 8) {
        const float4* pr = (const float4*)(p_att + ((long)b * Sn + s) * Hn);
        const float4* a4p = (const float4*)ah;
        const float4* w4p = (const float4*)wa;
        float local = 0.0f;
#pragma unroll
        for (int i = 0; i < 4; i++) {
            int h4 = i * 32 + lane;           // 0..127 float4 slots
            float4 p4 = pr[h4];
            float4 a4 = a4p[h4];
            float4 w4 = w4p[h4];
            local += fast_tanh(p4.x + a4.x) * w4.x;
            local += fast_tanh(p4.y + a4.y) * w4.y;
            local += fast_tanh(p4.z + a4.z) * w4.z;
            local += fast_tanh(p4.w + a4.w) * w4.w;
        }
#pragma unroll
        for (int o = 16; o > 0; o >>= 1)
            local += __shfl_xor_sync(0xffffffffu, local, o);
        if (lane == 0) sc[s] = local + balpha;
    }
    __syncthreads();

    // ---- block max ----
    float v = (tid < Sn) ? sc[tid] : -3.402823e38f;
    float m = v;
#pragma unroll
    for (int o = 16; o > 0; o >>= 1)
        m = fmaxf(m, __shfl_xor_sync(0xffffffffu, m, o));
    if (lane == 0) red[warp] = m;
    __syncthreads();
    if (warp == 0) {
        float t = (lane < 8) ? red[lane] : -3.402823e38f;
#pragma unroll
        for (int o = 4; o > 0; o >>= 1)
            t = fmaxf(t, __shfl_xor_sync(0xffffffffu, t, o));
        if (lane == 0) red[0] = t;
    }
    __syncthreads();
    m = __shfl_sync(0xffffffffu, red[0], 0);  // broadcast (all lanes read same)
    __syncthreads();

    // ---- exp + block sum ----
    float e = (tid < Sn) ? __expf(v - m) : 0.0f;
    float s1 = e;
#pragma unroll
    for (int o = 16; o > 0; o >>= 1)
        s1 += __shfl_xor_sync(0xffffffffu, s1, o);
    if (lane == 0) red[warp] = s1;
    __syncthreads();
    if (warp == 0) {
        float t = (lane < 8) ? red[lane] : 0.0f;
#pragma unroll
        for (int o = 4; o > 0; o >>= 1)
            t += __shfl_xor_sync(0xffffffffu, t, o);
        if (lane == 0) red[0] = t;
    }
    __syncthreads();
    float sum1 = red[0];
    __syncthreads();

    // ---- mask, renormalize ----
    float p = e / sum1;
    float pm = (tid < Sn) ? p * mask[b * Sn + tid] : 0.0f;
    float s2 = pm;
#pragma unroll
    for (int o = 16; o > 0; o >>= 1)
        s2 += __shfl_xor_sync(0xffffffffu, s2, o);
    if (lane == 0) red[warp] = s2;
    __syncthreads();
    if (warp == 0) {
        float t = (lane < 8) ? red[lane] : 0.0f;
#pragma unroll
        for (int o = 4; o > 0; o >>= 1)
            t += __shfl_xor_sync(0xffffffffu, t, o);
        if (lane == 0) red[0] = t;
    }
    __syncthreads();
    float sum2 = red[0];

    if (tid < Sn) g_weight[b * Sn + tid] = pm / sum2;
}

// ---------------------------------------------------------------------------
// Kernel 3: att_res[b,d] = sum_s weight[b,s] * att_feats[b,s,d]
// Grid (2, B): each block covers 1024 d's, 256 threads x float4.
// Unroll 4 over s -> 4 outstanding 16B loads/thread for DRAM latency hiding.
// ---------------------------------------------------------------------------
__global__ __launch_bounds__(256) void k_attres(const float* __restrict__ att_feats,
                                                float* __restrict__ out) {
    __shared__ float w[Sn];
    const int b = blockIdx.y;
    const int tid = threadIdx.x;
    if (tid < Sn) w[tid] = g_weight[b * Sn + tid];
    __syncthreads();

    const int d0 = blockIdx.x * 1024 + tid * 4;
    const float* base = att_feats + (long)b * Sn * Dn + d0;

    float4 acc = make_float4(0.f, 0.f, 0.f, 0.f);
#pragma unroll 4
    for (int s = 0; s < Sn; s++) {
        float4 f = *(const float4*)(base + (long)s * Dn);
        float ws = w[s];
        acc.x += ws * f.x;
        acc.y += ws * f.y;
        acc.z += ws * f.z;
        acc.w += ws * f.w;
    }
    *(float4*)(out + (long)b * Dn + d0) = acc;
}

// ---------------------------------------------------------------------------

extern "C" void kernel_launch(void* const* d_in, const int* in_sizes, int n_in,
                              void* d_out, int out_size) {
    const float* h         = (const float*)d_in[0];  // [B, D]
    const float* att_feats = (const float*)d_in[1];  // [B, S, D]
    const float* p_att     = (const float*)d_in[2];  // [B, S, H]
    const float* mask      = (const float*)d_in[3];  // [B, S]
    const float* W_h2att   = (const float*)d_in[4];  // [H, D]
    const float* b_h2att   = (const float*)d_in[5];  // [H]
    const float* w_alpha   = (const float*)d_in[6];  // [H]
    const float* b_alpha   = (const float*)d_in[7];  // scalar
    float* out = (float*)d_out;                      // [B, D]

    (void)in_sizes; (void)n_in; (void)out_size;

    dim3 g1(Hn / 32, Bn / 32);  // (16, 8)
    k_h2att<<<g1, 128>>>(h, W_h2att, b_h2att);

    k_scores<<<Bn, 256>>>(p_att, w_alpha, b_alpha, mask);

    dim3 g3(Dn / 1024, Bn);     // (2, 256)
    k_attres<<<g3, 256>>>(att_feats, out);
}

// round 2
// speedup vs baseline: 1.8678x; 1.8678x over previous
#include <cuda_runtime.h>

#define Bn 256
#define Sn 196
#define Dn 2048
#define Hn 512
#define KSPLIT 8
#define KCHUNK (Dn / KSPLIT)   // 256

// Scratch (no cudaMalloc allowed)
__device__ float g_atth_part[KSPLIT * Bn * Hn];  // 4 MB split-K partials
__device__ float g_scores[Bn * Sn];
__device__ float g_weight[Bn * Sn];

// tanh via 1 - 2/(e^{2x}+1): one MUFU.EX2 + one MUFU.RCP, abs err ~1e-6.
__device__ __forceinline__ float fast_tanh(float x) {
    float t = __expf(2.0f * x);
    return 1.0f - 2.0f / (t + 1.0f);
}

// ---------------------------------------------------------------------------
// Kernel 1: split-K GEMM partials.
//   part[z][m][n] = sum_{k in chunk z} h[m,k] * W[n,k]
// M=256, N=512, K-chunk=256. 32x32 tile, 128 threads, 4x2/thread.
// Grid (16, 8, 8) = 1024 blocks -> ~28 warps/SM (vs 3.5 before).
// ---------------------------------------------------------------------------
__global__ __launch_bounds__(128) void k_h2att_sk(const float* __restrict__ A,
                                                  const float* __restrict__ W) {
    __shared__ float As[32 * 36];  // [k][m], pad 36 keeps float4 alignment per row
    __shared__ float Bs[32 * 34];  // [k][n], pad 34 keeps float2 alignment per row
    const int tid = threadIdx.x;
    const int tx = tid & 15;   // n group (2 cols)
    const int ty = tid >> 4;   // m group (4 rows)
    const int m0 = blockIdx.y * 32;
    const int n0 = blockIdx.x * 32;
    const int kbase = blockIdx.z * KCHUNK;

    float acc[4][2] = {};

    for (int kt = 0; kt < KCHUNK; kt += 32) {
        const int k0 = kbase + kt;
#pragma unroll
        for (int i = 0; i < 8; i++) {
            int idx = i * 128 + tid;
            int r = idx >> 5;      // row within tile (m or n)
            int c = idx & 31;      // k within tile (contiguous -> coalesced gmem)
            As[c * 36 + r] = A[(m0 + r) * Dn + k0 + c];
            Bs[c * 34 + r] = W[(n0 + r) * Dn + k0 + c];
        }
        __syncthreads();
#pragma unroll
        for (int k = 0; k < 32; k++) {
            float4 a = *(const float4*)&As[k * 36 + ty * 4];
            float2 b = *(const float2*)&Bs[k * 34 + tx * 2];
            acc[0][0] += a.x * b.x; acc[0][1] += a.x * b.y;
            acc[1][0] += a.y * b.x; acc[1][1] += a.y * b.y;
            acc[2][0] += a.z * b.x; acc[2][1] += a.z * b.y;
            acc[3][0] += a.w * b.x; acc[3][1] += a.w * b.y;
        }
        __syncthreads();
    }

    float* dst = g_atth_part + (size_t)blockIdx.z * (Bn * Hn);
#pragma unroll
    for (int i = 0; i < 4; i++)
#pragma unroll
        for (int j = 0; j < 2; j++)
            dst[(m0 + ty * 4 + i) * Hn + n0 + tx * 2 + j] = acc[i][j];
}

// ---------------------------------------------------------------------------
// Kernel 2: raw scores. Grid (B, 7): block covers 28 s-slots, warp per slot.
//   scores[b,s] = sum_h tanh(p[b,s,h] + att_h[b,h]) * w_alpha[h] + b_alpha
// att_h assembled here from the 8 split-K partials + bias (L2-hit loads).
// ---------------------------------------------------------------------------
__global__ __launch_bounds__(256) void k_scores_part(const float* __restrict__ p_att,
                                                     const float* __restrict__ w_alpha,
                                                     const float* __restrict__ bias,
                                                     const float* __restrict__ b_alpha) {
    __shared__ float ah[Hn];
    __shared__ float wa[Hn];

    const int b = blockIdx.x;
    const int sgrp = blockIdx.y;          // 0..6, 28 slots each
    const int tid = threadIdx.x;
    const int lane = tid & 31;
    const int warp = tid >> 5;

#pragma unroll
    for (int h = tid; h < Hn; h += 256) {
        float acc = bias[h];
#pragma unroll
        for (int z = 0; z < KSPLIT; z++)
            acc += g_atth_part[z * (Bn * Hn) + b * Hn + h];
        ah[h] = acc;
        wa[h] = w_alpha[h];
    }
    __syncthreads();

    const float balpha = b_alpha[0];
    const float4* a4p = (const float4*)ah;
    const float4* w4p = (const float4*)wa;

    for (int ss = warp; ss < 28; ss += 8) {
        const int s = sgrp * 28 + ss;
        const float4* pr = (const float4*)(p_att + ((long)b * Sn + s) * Hn);
        float local = 0.0f;
#pragma unroll
        for (int i = 0; i < 4; i++) {
            int h4 = i * 32 + lane;        // 0..127 float4 slots
            float4 p4 = pr[h4];
            float4 a4 = a4p[h4];
            float4 w4 = w4p[h4];
            local += fast_tanh(p4.x + a4.x) * w4.x;
            local += fast_tanh(p4.y + a4.y) * w4.y;
            local += fast_tanh(p4.z + a4.z) * w4.z;
            local += fast_tanh(p4.w + a4.w) * w4.w;
        }
#pragma unroll
        for (int o = 16; o > 0; o >>= 1)
            local += __shfl_xor_sync(0xffffffffu, local, o);
        if (lane == 0) g_scores[b * Sn + s] = local + balpha;
    }
}

// ---------------------------------------------------------------------------
// Kernel 3: masked softmax over S. Grid B, 256 threads. Tiny (200 KB total).
// ---------------------------------------------------------------------------
__global__ __launch_bounds__(256) void k_softmax(const float* __restrict__ mask) {
    __shared__ float red[8];
    const int b = blockIdx.x;
    const int tid = threadIdx.x;
    const int lane = tid & 31;
    const int warp = tid >> 5;

    float v = (tid < Sn) ? g_scores[b * Sn + tid] : -3.402823e38f;

    // block max
    float m = v;
#pragma unroll
    for (int o = 16; o > 0; o >>= 1)
        m = fmaxf(m, __shfl_xor_sync(0xffffffffu, m, o));
    if (lane == 0) red[warp] = m;
    __syncthreads();
    if (warp == 0) {
        float t = (lane < 8) ? red[lane] : -3.402823e38f;
#pragma unroll
        for (int o = 4; o > 0; o >>= 1)
            t = fmaxf(t, __shfl_xor_sync(0xffffffffu, t, o));
        if (lane == 0) red[0] = t;
    }
    __syncthreads();
    m = red[0];
    __syncthreads();

    // exp + block sum
    float e = (tid < Sn) ? __expf(v - m) : 0.0f;
    float s1 = e;
#pragma unroll
    for (int o = 16; o > 0; o >>= 1)
        s1 += __shfl_xor_sync(0xffffffffu, s1, o);
    if (lane == 0) red[warp] = s1;
    __syncthreads();
    if (warp == 0) {
        float t = (lane < 8) ? red[lane] : 0.0f;
#pragma unroll
        for (int o = 4; o > 0; o >>= 1)
            t += __shfl_xor_sync(0xffffffffu, t, o);
        if (lane == 0) red[0] = t;
    }
    __syncthreads();
    float sum1 = red[0];
    __syncthreads();

    // mask + renormalize
    float pm = (tid < Sn) ? (e / sum1) * mask[b * Sn + tid] : 0.0f;
    float s2 = pm;
#pragma unroll
    for (int o = 16; o > 0; o >>= 1)
        s2 += __shfl_xor_sync(0xffffffffu, s2, o);
    if (lane == 0) red[warp] = s2;
    __syncthreads();
    if (warp == 0) {
        float t = (lane < 8) ? red[lane] : 0.0f;
#pragma unroll
        for (int o = 4; o > 0; o >>= 1)
            t += __shfl_xor_sync(0xffffffffu, t, o);
        if (lane == 0) red[0] = t;
    }
    __syncthreads();

    if (tid < Sn) g_weight[b * Sn + tid] = pm / red[0];
}

// ---------------------------------------------------------------------------
// Kernel 4: att_res[b,d] = sum_s weight[b,s] * att_feats[b,s,d]
// Grid (4, B) = 1024 blocks x 128 threads, float4/thread, unroll 8
// -> ~28 warps/SM with 8 outstanding 16B loads each; DRAM-floor bound.
// ---------------------------------------------------------------------------
__global__ __launch_bounds__(128) void k_attres(const float* __restrict__ att_feats,
                                                float* __restrict__ out) {
    __shared__ float w[Sn];
    const int b = blockIdx.y;
    const int tid = threadIdx.x;
    for (int i = tid; i < Sn; i += 128) w[i] = g_weight[b * Sn + i];
    __syncthreads();

    const int d0 = blockIdx.x * 512 + tid * 4;
    const float* base = att_feats + (long)b * Sn * Dn + d0;

    float4 acc = make_float4(0.f, 0.f, 0.f, 0.f);
#pragma unroll 8
    for (int s = 0; s < Sn; s++) {
        float4 f = *(const float4*)(base + (long)s * Dn);
        float ws = w[s];
        acc.x += ws * f.x;
        acc.y += ws * f.y;
        acc.z += ws * f.z;
        acc.w += ws * f.w;
    }
    *(float4*)(out + (long)b * Dn + d0) = acc;
}

// ---------------------------------------------------------------------------

extern "C" void kernel_launch(void* const* d_in, const int* in_sizes, int n_in,
                              void* d_out, int out_size) {
    const float* h         = (const float*)d_in[0];  // [B, D]
    const float* att_feats = (const float*)d_in[1];  // [B, S, D]
    const float* p_att     = (const float*)d_in[2];  // [B, S, H]
    const float* mask      = (const float*)d_in[3];  // [B, S]
    const float* W_h2att   = (const float*)d_in[4];  // [H, D]
    const float* b_h2att   = (const float*)d_in[5];  // [H]
    const float* w_alpha   = (const float*)d_in[6];  // [H]
    const float* b_alpha   = (const float*)d_in[7];  // scalar
    float* out = (float*)d_out;                      // [B, D]

    (void)in_sizes; (void)n_in; (void)out_size;

    dim3 g1(Hn / 32, Bn / 32, KSPLIT);  // (16, 8, 8) = 1024 blocks
    k_h2att_sk<<<g1, 128>>>(h, W_h2att);

    dim3 g2(Bn, 7);                     // 1792 blocks
    k_scores_part<<<g2, 256>>>(p_att, w_alpha, b_h2att, b_alpha);

    k_softmax<<<Bn, 256>>>(mask);

    dim3 g4(4, Bn);                     // 1024 blocks
    k_attres<<<g4, 128>>>(att_feats, out);
}